// round 9
// baseline (speedup 1.0000x reference)
#include <cuda_runtime.h>
#include <cuda_bf16.h>

// IDWT 2D (inverse Haar), reference-exact layout. R3 access shape (best:
// 43.8us, DRAM 70.9%) made PERSISTENT: exactly one wave of CTAs (148 SMs x
// occ 8 = 1184 CTAs), each grid-striding over the work. Eliminates ~13 wave
// transitions / launch-drain churn of the 16384-CTA version while keeping
// the per-iteration memory shape identical (4x front-batched LDG.64 +
// 2x STG.128, stride multiple of warp width so coalescing is unchanged).
//
// Input x: (B=8, 4*C=256, H=128, W=128) fp32 -> Output (8, 64, 256, 256) fp32.
// Mapping from the reference's raw (H,W,2,2)->(2H,2W) reshape:
//   input (i,j) -> float4 at row = 2i + (j>=64), col = 4*(j mod 64)
//   butterfly = (ll+lh+hl+hh, ll+lh-hl-hh, ll-lh+hl-hh, ll-lh-hl+hh)

static constexpr int B  = 8;
static constexpr int C  = 64;
static constexpr int H  = 128;
static constexpr int W  = 128;
static constexpr int JV = W / 2;   // 64 j-pairs per input row

static constexpr unsigned BAND_STRIDE = (unsigned)C * H * W;      // 1,048,576
static constexpr unsigned X_N_STRIDE  = 4u * BAND_STRIDE;
static constexpr unsigned O_C_STRIDE  = 2u * H * 2u * W;          // 65,536
static constexpr unsigned O_N_STRIDE  = (unsigned)C * O_C_STRIDE;

static constexpr unsigned TOTAL   = (unsigned)B * C * H * JV;     // 4,194,304
static constexpr int      THREADS = 256;
static constexpr int      BLOCKS  = 148 * 8;                      // one full wave

__global__ void __launch_bounds__(THREADS) idwt2d_kernel(const float* __restrict__ x,
                                                         float* __restrict__ out)
{
    const unsigned stride = (unsigned)BLOCKS * THREADS;   // 303,104

    for (unsigned tid = blockIdx.x * THREADS + threadIdx.x;
         tid < TOTAL; tid += stride)
    {
        unsigned jv = tid & (JV - 1);        // 0..63  -> j = 2jv, 2jv+1
        unsigned t1 = tid >> 6;
        unsigned i  = t1 & (H - 1);          // 0..127
        unsigned t2 = t1 >> 7;
        unsigned c  = t2 & (C - 1);          // 0..63
        unsigned n  = t2 >> 6;               // 0..7

        unsigned xbase = n * X_N_STRIDE + c * (H * W) + i * W + 2 * jv;

        float2 ll = *(const float2*)(x + xbase + 0 * BAND_STRIDE);
        float2 lh = *(const float2*)(x + xbase + 1 * BAND_STRIDE);
        float2 hl = *(const float2*)(x + xbase + 2 * BAND_STRIDE);
        float2 hh = *(const float2*)(x + xbase + 3 * BAND_STRIDE);

        // butterfly for j = 2jv (x) and j = 2jv+1 (y)
        float sA0 = ll.x + lh.x, dA0 = ll.x - lh.x;
        float sB0 = hl.x + hh.x, dB0 = hl.x - hh.x;
        float sA1 = ll.y + lh.y, dA1 = ll.y - lh.y;
        float sB1 = hl.y + hh.y, dB1 = hl.y - hh.y;

        float4 q0, q1;
        q0.x = sA0 + sB0;   // (a,b)=(0,0)
        q0.y = sA0 - sB0;   // (0,1)
        q0.z = dA0 + dB0;   // (1,0)
        q0.w = dA0 - dB0;   // (1,1)

        q1.x = sA1 + sB1;
        q1.y = sA1 - sB1;
        q1.z = dA1 + dB1;
        q1.w = dA1 - dB1;

        // j = 2jv -> row = 2i + (jv>=32), col = 4*((2jv) mod 64)
        unsigned jhalf = jv >> 5;
        unsigned col   = (2 * jv - jhalf * 64) * 4;

        unsigned obase = n * O_N_STRIDE + c * O_C_STRIDE
                       + (2 * i + jhalf) * (2 * W) + col;

        *(float4*)(out + obase)     = q0;
        *(float4*)(out + obase + 4) = q1;
    }
}

extern "C" void kernel_launch(void* const* d_in, const int* in_sizes, int n_in,
                              void* d_out, int out_size)
{
    const float* x = (const float*)d_in[0];
    float* out = (float*)d_out;

    idwt2d_kernel<<<BLOCKS, THREADS>>>(x, out);
}

// round 10
// speedup vs baseline: 1.2312x; 1.2312x over previous
#include <cuda_runtime.h>
#include <cuda_bf16.h>

// IDWT 2D (inverse Haar), reference-exact layout — FINAL (R3 shape, measured
// best across 7 variants: 43.8us, DRAM 70.9% = mixed R/W HBM3e plateau).
//
// Input x: (B=8, 4*C=256, H=128, W=128) fp32 -> Output (8, 64, 256, 256) fp32.
//
// Reference does y[n,c,i,j,a,b] = sum_k f[k,a,b] * x[n,kC+c,i,j] then a raw
// reshape of (H,W,2,2) -> (2H,2W). Flat index ((i*W+j)*2+a)*2+b over rows of
// width 2W=256 gives:
//   j in [0,64):   row = 2i,   col = 4j      + 2a + b
//   j in [64,128): row = 2i+1, col = 4(j-64) + 2a + b
// Butterfly (a,b) order: (ll+lh+hl+hh, ll+lh-hl-hh, ll-lh+hl-hh, ll-lh-hl+hh).
//
// One thread per j-pair: 4 front-batched LDG.64 (256B dense per warp per
// band) + 2 contiguous STG.128. Both read and write streams are perfectly
// address-sequential in tid. Flat grid (no persistence: grid-stride loops
// serialize MLP, measured -23%); no L2 hints (measured neutral); no wider
// accesses (measured -5..-12% DRAM%).

static constexpr int B  = 8;
static constexpr int C  = 64;
static constexpr int H  = 128;
static constexpr int W  = 128;
static constexpr int JV = W / 2;   // 64 j-pairs per input row

static constexpr long long BAND_STRIDE = (long long)C * H * W;   // 1,048,576
static constexpr long long X_N_STRIDE  = 4LL * BAND_STRIDE;
static constexpr long long O_C_STRIDE  = 2LL * H * 2LL * W;      // 65,536
static constexpr long long O_N_STRIDE  = (long long)C * O_C_STRIDE;

__global__ void idwt2d_kernel(const float* __restrict__ x,
                              float* __restrict__ out)
{
    // total threads = B*C*H*JV = 4,194,304; one thread per j-pair
    int tid = blockIdx.x * blockDim.x + threadIdx.x;

    int jv = tid & (JV - 1);         // 0..63  -> j = 2jv, 2jv+1
    int t1 = tid >> 6;
    int i  = t1 & (H - 1);           // 0..127
    int t2 = t1 >> 7;
    int c  = t2 & (C - 1);           // 0..63
    int n  = t2 >> 6;                // 0..7

    long long xbase = (long long)n * X_N_STRIDE
                    + (long long)c * H * W
                    + (long long)i * W
                    + 2 * jv;

    float2 ll = __ldg((const float2*)(x + xbase + 0 * BAND_STRIDE));
    float2 lh = __ldg((const float2*)(x + xbase + 1 * BAND_STRIDE));
    float2 hl = __ldg((const float2*)(x + xbase + 2 * BAND_STRIDE));
    float2 hh = __ldg((const float2*)(x + xbase + 3 * BAND_STRIDE));

    // butterfly for j = 2jv (x) and j = 2jv+1 (y)
    float sA0 = ll.x + lh.x, dA0 = ll.x - lh.x;
    float sB0 = hl.x + hh.x, dB0 = hl.x - hh.x;
    float sA1 = ll.y + lh.y, dA1 = ll.y - lh.y;
    float sB1 = hl.y + hh.y, dB1 = hl.y - hh.y;

    float4 q0, q1;
    q0.x = sA0 + sB0;   // (a,b)=(0,0)
    q0.y = sA0 - sB0;   // (0,1)
    q0.z = dA0 + dB0;   // (1,0)
    q0.w = dA0 - dB0;   // (1,1)

    q1.x = sA1 + sB1;
    q1.y = sA1 - sB1;
    q1.z = dA1 + dB1;
    q1.w = dA1 - dB1;

    // j = 2jv -> row = 2i + (jv>=32), col = 4*((2jv) mod 64)
    int jhalf = jv >> 5;
    int col   = (2 * jv - jhalf * 64) * 4;

    long long obase = (long long)n * O_N_STRIDE
                    + (long long)c * O_C_STRIDE
                    + (long long)(2 * i + jhalf) * (2 * W)
                    + col;

    *(float4*)(out + obase)     = q0;
    *(float4*)(out + obase + 4) = q1;
}

extern "C" void kernel_launch(void* const* d_in, const int* in_sizes, int n_in,
                              void* d_out, int out_size)
{
    const float* x = (const float*)d_in[0];
    float* out = (float*)d_out;

    const int total = B * C * H * JV;   // 4,194,304
    const int threads = 256;
    const int blocks = total / threads; // 16384

    idwt2d_kernel<<<blocks, threads>>>(x, out);
}

// round 11
// speedup vs baseline: 1.2384x; 1.0059x over previous
#include <cuda_runtime.h>
#include <cuda_bf16.h>

// IDWT 2D (inverse Haar), reference-exact layout. R3 shape (measured best:
// 43.7us, DRAM ~70%) + ONE change: output stores use st.global.cs
// (evict-first). Output lines are write-once-dead; demoting them frees L2
// ways for the input read stream, which already shows opportunistic L2 hits
// (DRAM counter 5.5 TB/s < logical 6.9 TB/s service rate). Loads stay
// default (R4 showed __ldcs scalar loads regress; R7 showed pinning input
// is self-thrashing at 128MB vs 126MB L2).
//
// Input x: (B=8, 4*C=256, H=128, W=128) fp32 -> Output (8, 64, 256, 256) fp32.
// Mapping from the reference's raw (H,W,2,2)->(2H,2W) reshape:
//   j in [0,64):   row = 2i,   col = 4j       (+2a+b)
//   j in [64,128): row = 2i+1, col = 4(j-64)  (+2a+b)
// Butterfly order: (ll+lh+hl+hh, ll+lh-hl-hh, ll-lh+hl-hh, ll-lh-hl+hh).

static constexpr int B  = 8;
static constexpr int C  = 64;
static constexpr int H  = 128;
static constexpr int W  = 128;
static constexpr int JV = W / 2;   // 64 j-pairs per input row

static constexpr long long BAND_STRIDE = (long long)C * H * W;   // 1,048,576
static constexpr long long X_N_STRIDE  = 4LL * BAND_STRIDE;
static constexpr long long O_C_STRIDE  = 2LL * H * 2LL * W;      // 65,536
static constexpr long long O_N_STRIDE  = (long long)C * O_C_STRIDE;

__global__ void idwt2d_kernel(const float* __restrict__ x,
                              float* __restrict__ out)
{
    // total threads = B*C*H*JV = 4,194,304; one thread per j-pair
    int tid = blockIdx.x * blockDim.x + threadIdx.x;

    int jv = tid & (JV - 1);         // 0..63  -> j = 2jv, 2jv+1
    int t1 = tid >> 6;
    int i  = t1 & (H - 1);           // 0..127
    int t2 = t1 >> 7;
    int c  = t2 & (C - 1);           // 0..63
    int n  = t2 >> 6;                // 0..7

    long long xbase = (long long)n * X_N_STRIDE
                    + (long long)c * H * W
                    + (long long)i * W
                    + 2 * jv;

    float2 ll = __ldg((const float2*)(x + xbase + 0 * BAND_STRIDE));
    float2 lh = __ldg((const float2*)(x + xbase + 1 * BAND_STRIDE));
    float2 hl = __ldg((const float2*)(x + xbase + 2 * BAND_STRIDE));
    float2 hh = __ldg((const float2*)(x + xbase + 3 * BAND_STRIDE));

    // butterfly for j = 2jv (x) and j = 2jv+1 (y)
    float sA0 = ll.x + lh.x, dA0 = ll.x - lh.x;
    float sB0 = hl.x + hh.x, dB0 = hl.x - hh.x;
    float sA1 = ll.y + lh.y, dA1 = ll.y - lh.y;
    float sB1 = hl.y + hh.y, dB1 = hl.y - hh.y;

    float4 q0, q1;
    q0.x = sA0 + sB0;   // (a,b)=(0,0)
    q0.y = sA0 - sB0;   // (0,1)
    q0.z = dA0 + dB0;   // (1,0)
    q0.w = dA0 - dB0;   // (1,1)

    q1.x = sA1 + sB1;
    q1.y = sA1 - sB1;
    q1.z = dA1 + dB1;
    q1.w = dA1 - dB1;

    // j = 2jv -> row = 2i + (jv>=32), col = 4*((2jv) mod 64)
    int jhalf = jv >> 5;
    int col   = (2 * jv - jhalf * 64) * 4;

    long long obase = (long long)n * O_N_STRIDE
                    + (long long)c * O_C_STRIDE
                    + (long long)(2 * i + jhalf) * (2 * W)
                    + col;

    __stcs((float4*)(out + obase),     q0);
    __stcs((float4*)(out + obase + 4), q1);
}

extern "C" void kernel_launch(void* const* d_in, const int* in_sizes, int n_in,
                              void* d_out, int out_size)
{
    const float* x = (const float*)d_in[0];
    float* out = (float*)d_out;

    const int total = B * C * H * JV;   // 4,194,304
    const int threads = 256;
    const int blocks = total / threads; // 16384

    idwt2d_kernel<<<blocks, threads>>>(x, out);
}